// round 16
// baseline (speedup 1.0000x reference)
#include <cuda_runtime.h>
#include <math.h>
#include <stdint.h>

// out[b,k] = exp(-beta_k * max(||x_b||^2 + ||c_k||^2 - 2 x_b.c_k, 0))
// B=16384, K=4096, D=1024, fp32.
//
// fp32 exp(-t) == exactly 0.0f for t > ~104. Cauchy-Schwarz: d2 >= (||x_b||-||c_k||)^2.
// Per-column interval [lo_k, hi_k] of ||x|| for which an element is NOT provably
// zero; global interval over k. Rows with ||x_b|| outside the global interval
// are provably all-zero (exact interval-test + dot + expf fallback otherwise).
//
// Measured store-path law on this chip (R1..R15):
//   fast regime  : flat grid, ONE float4 store per thread, store-and-exit (~770 GB/s)
//   slow regimes : looped STG, CE memset, TMA bulk, v8 stores, thin blocks
// This round keeps the per-thread contract and raises threads/block to 1024
// (one row per block, 16384 blocks) + streaming (.cs) hint on the zero store.

#define B_ROWS 16384
#define K_COLS 4096
#define D_DIM  1024
#define THRESH 106.0f

__device__ float g_x2[B_ROWS];
__device__ float g_rx[B_ROWS];
__device__ float g_c2[K_COLS];
__device__ float g_lo[K_COLS];
__device__ float g_hi[K_COLS];
__device__ float g_glo;
__device__ float g_ghi;

// ---------------------------------------------------------------------------
// Kernel 1: row norms. Rows [0,K): centers -> c2, lo, hi. Rows [K,K+B): x -> x2, rx.
// ---------------------------------------------------------------------------
__global__ void __launch_bounds__(256) norms_kernel(const float* __restrict__ x,
                                                    const float* __restrict__ c,
                                                    const float* __restrict__ betas) {
    const int row = blockIdx.x;
    const bool is_center = (row < K_COLS);
    const float* src = is_center ? (c + (size_t)row * D_DIM)
                                 : (x + (size_t)(row - K_COLS) * D_DIM);
    const int tid = threadIdx.x;
    float4 a = reinterpret_cast<const float4*>(src)[tid];
    float s = a.x * a.x + a.y * a.y + a.z * a.z + a.w * a.w;
    #pragma unroll
    for (int o = 16; o > 0; o >>= 1)
        s += __shfl_xor_sync(0xffffffffu, s, o);
    __shared__ float ws[8];
    if ((tid & 31) == 0) ws[tid >> 5] = s;
    __syncthreads();
    if (tid == 0) {
        float t = 0.f;
        #pragma unroll
        for (int i = 0; i < 8; i++) t += ws[i];
        if (is_center) {
            g_c2[row] = t;
            const float beta = betas[row];
            const float sk = sqrtf(t);
            float lo = -INFINITY, hi = INFINITY;
            if (beta > 0.0f && isfinite(sk)) {
                const float rk = sqrtf(THRESH / beta);
                if (isfinite(rk)) { lo = sk - rk; hi = sk + rk; }
            }
            if (!(lo == lo)) lo = -INFINITY;   // NaN -> always-exact interval
            if (!(hi == hi)) hi =  INFINITY;
            g_lo[row] = lo;
            g_hi[row] = hi;
        } else {
            g_x2[row - K_COLS] = t;
            g_rx[row - K_COLS] = sqrtf(t);
        }
    }
}

// ---------------------------------------------------------------------------
// Kernel 2: global interval reduce.
// ---------------------------------------------------------------------------
__global__ void __launch_bounds__(256) glob_kernel() {
    __shared__ float slo[256], shi[256];
    float lo = INFINITY, hi = -INFINITY;
    for (int k = threadIdx.x; k < K_COLS; k += 256) {
        lo = fminf(lo, g_lo[k]);
        hi = fmaxf(hi, g_hi[k]);
    }
    slo[threadIdx.x] = lo;
    shi[threadIdx.x] = hi;
    __syncthreads();
    for (int s2 = 128; s2 > 0; s2 >>= 1) {
        if (threadIdx.x < s2) {
            slo[threadIdx.x] = fminf(slo[threadIdx.x], slo[threadIdx.x + s2]);
            shi[threadIdx.x] = fmaxf(shi[threadIdx.x], shi[threadIdx.x + s2]);
        }
        __syncthreads();
    }
    if (threadIdx.x == 0) { g_glo = slo[0]; g_ghi = shi[0]; }
}

// ---------------------------------------------------------------------------
// Kernel 3: main. One block per row: 16384 blocks x 1024 threads.
// Fast path: ONE streaming float4 store per thread (thread tid owns columns
// [tid*4, tid*4+4) of the row), then exit. No loops, no smem, no barriers.
// Slow path (block-uniform, rare): exact interval test + fp32 dot + expf,
// still exactly one float4 store per thread.
// ---------------------------------------------------------------------------
__global__ void __launch_bounds__(1024) rbf_main(const float* __restrict__ x,
                                                 const float* __restrict__ c,
                                                 const float* __restrict__ betas,
                                                 float* __restrict__ out) {
    const int tid = threadIdx.x;
    const int b   = blockIdx.x;
    float4* __restrict__ optr =
        reinterpret_cast<float4*>(out + ((size_t)b << 12)) + tid;

    const float t = g_rx[b];
    if (t < g_glo || t > g_ghi) {
        // provably-zero row: one streaming 128-bit store, exit. (NaN falls through)
        __stcs(optr, make_float4(0.f, 0.f, 0.f, 0.f));
        return;
    }

    // Exact path (block-uniform branch; statistically ~1e-3 of rows).
    __shared__ float xs[D_DIM];
    if (tid < 256)
        reinterpret_cast<float4*>(xs)[tid] =
            reinterpret_cast<const float4*>(x + (size_t)b * D_DIM)[tid];
    __syncthreads();
    const float sx = g_x2[b];

    const int kq = tid;                                     // float4 column group
    const float4 lo4 = reinterpret_cast<const float4*>(g_lo)[kq];
    const float4 hi4 = reinterpret_cast<const float4*>(g_hi)[kq];
    const float4 c24 = reinterpret_cast<const float4*>(g_c2)[kq];
    const float4 bt4 = reinterpret_cast<const float4*>(betas)[kq];
    const float lo_a[4] = {lo4.x, lo4.y, lo4.z, lo4.w};
    const float hi_a[4] = {hi4.x, hi4.y, hi4.z, hi4.w};
    const float c2_a[4] = {c24.x, c24.y, c24.z, c24.w};
    const float bt_a[4] = {bt4.x, bt4.y, bt4.z, bt4.w};
    float o[4];
    #pragma unroll
    for (int q = 0; q < 4; q++) {
        if (t < lo_a[q] || t > hi_a[q]) {
            o[q] = 0.0f;                                    // provably underflows
        } else {
            const float* __restrict__ cr = c + (size_t)(kq * 4 + q) * D_DIM;
            float dot = 0.f;
            #pragma unroll 8
            for (int i = 0; i < D_DIM; i++) dot = fmaf(xs[i], cr[i], dot);
            const float d2 = fmaxf(sx + c2_a[q] - 2.0f * dot, 0.0f);
            o[q] = expf(-bt_a[q] * d2);
        }
    }
    *optr = make_float4(o[0], o[1], o[2], o[3]);
}

// ---------------------------------------------------------------------------
extern "C" void kernel_launch(void* const* d_in, const int* in_sizes, int n_in,
                              void* d_out, int out_size) {
    const float* x     = (const float*)d_in[0];
    const float* cent  = (const float*)d_in[1];
    const float* betas = (const float*)d_in[2];
    float* out = (float*)d_out;

    norms_kernel<<<K_COLS + B_ROWS, 256>>>(x, cent, betas);
    glob_kernel<<<1, 256>>>();
    rbf_main<<<B_ROWS, 1024>>>(x, cent, betas, out);
}

// round 17
// speedup vs baseline: 1.4366x; 1.4366x over previous
#include <cuda_runtime.h>
#include <math.h>
#include <stdint.h>

// out[b,k] = exp(-beta_k * max(||x_b||^2 + ||c_k||^2 - 2 x_b.c_k, 0))
// B=16384, K=4096, D=1024, fp32.
//
// fp32 exp(-t) == exactly 0.0f for t > ~104. Cauchy-Schwarz: d2 >= (||x_b||-||c_k||)^2.
// Per-column interval [lo_k, hi_k] of ||x|| for which an element is NOT provably
// zero; global interval over k. Rows with ||x_b|| outside the global interval are
// provably all-zero; others are recomputed exactly by fixup (interval test +
// fp32 dot + expf). Correct for arbitrary inputs.
//
// Measured store-path law (R1..R16): the ONLY fast fill shape on this chip is
// 65536 CTAs x 256 thr x one plain STG.128 (~350us); everything else (loops,
// memset, TMA, v8, other block sizes, .cs) is 1.7-5x slower, with DRAM idle ->
// per-CTA lifetime bound. This round strips the fill to the irreducible
// minimum (no loads, no branches, ~6 regs) to maximize CTA residency, and
// moves ALL correctness work into the post-pass fixup (measured 1.2us).

#define B_ROWS 16384
#define K_COLS 4096
#define D_DIM  1024
#define THRESH 106.0f

__device__ float g_x2[B_ROWS];
__device__ float g_rx[B_ROWS];
__device__ float g_c2[K_COLS];
__device__ float g_lo[K_COLS];
__device__ float g_hi[K_COLS];
__device__ float g_glo;
__device__ float g_ghi;

// ---------------------------------------------------------------------------
// Kernel 0: unconditional zero-fill. The irreducible fast-shape store kernel:
// one float4 store per thread, no loads, no branches, no smem.
// ---------------------------------------------------------------------------
__global__ void __launch_bounds__(256) zfill(float4* __restrict__ out) {
    out[(((size_t)blockIdx.y * 4 + blockIdx.x) << 8) + threadIdx.x] =
        make_float4(0.f, 0.f, 0.f, 0.f);
}

// ---------------------------------------------------------------------------
// Kernel 1: row norms. Rows [0,K): centers -> c2, lo, hi. Rows [K,K+B): x -> x2, rx.
// ---------------------------------------------------------------------------
__global__ void __launch_bounds__(256) norms_kernel(const float* __restrict__ x,
                                                    const float* __restrict__ c,
                                                    const float* __restrict__ betas) {
    const int row = blockIdx.x;
    const bool is_center = (row < K_COLS);
    const float* src = is_center ? (c + (size_t)row * D_DIM)
                                 : (x + (size_t)(row - K_COLS) * D_DIM);
    const int tid = threadIdx.x;
    float4 a = reinterpret_cast<const float4*>(src)[tid];
    float s = a.x * a.x + a.y * a.y + a.z * a.z + a.w * a.w;
    #pragma unroll
    for (int o = 16; o > 0; o >>= 1)
        s += __shfl_xor_sync(0xffffffffu, s, o);
    __shared__ float ws[8];
    if ((tid & 31) == 0) ws[tid >> 5] = s;
    __syncthreads();
    if (tid == 0) {
        float t = 0.f;
        #pragma unroll
        for (int i = 0; i < 8; i++) t += ws[i];
        if (is_center) {
            g_c2[row] = t;
            const float beta = betas[row];
            const float sk = sqrtf(t);
            float lo = -INFINITY, hi = INFINITY;
            if (beta > 0.0f && isfinite(sk)) {
                const float rk = sqrtf(THRESH / beta);
                if (isfinite(rk)) { lo = sk - rk; hi = sk + rk; }
            }
            if (!(lo == lo)) lo = -INFINITY;   // NaN -> always-exact interval
            if (!(hi == hi)) hi =  INFINITY;
            g_lo[row] = lo;
            g_hi[row] = hi;
        } else {
            g_x2[row - K_COLS] = t;
            g_rx[row - K_COLS] = sqrtf(t);
        }
    }
}

// ---------------------------------------------------------------------------
// Kernel 2: global interval reduce.
// ---------------------------------------------------------------------------
__global__ void __launch_bounds__(256) glob_kernel() {
    __shared__ float slo[256], shi[256];
    float lo = INFINITY, hi = -INFINITY;
    for (int k = threadIdx.x; k < K_COLS; k += 256) {
        lo = fminf(lo, g_lo[k]);
        hi = fmaxf(hi, g_hi[k]);
    }
    slo[threadIdx.x] = lo;
    shi[threadIdx.x] = hi;
    __syncthreads();
    for (int s2 = 128; s2 > 0; s2 >>= 1) {
        if (threadIdx.x < s2) {
            slo[threadIdx.x] = fminf(slo[threadIdx.x], slo[threadIdx.x + s2]);
            shi[threadIdx.x] = fmaxf(shi[threadIdx.x], shi[threadIdx.x + s2]);
        }
        __syncthreads();
    }
    if (threadIdx.x == 0) { g_glo = slo[0]; g_ghi = shi[0]; }
}

// ---------------------------------------------------------------------------
// Kernel 3: fixup. One block per row; early-exit when the row is provably zero
// (measured ~1.2us for the whole grid). Otherwise recompute the full row
// exactly and overwrite the zeros written by zfill (same stream -> ordered).
// ---------------------------------------------------------------------------
__global__ void __launch_bounds__(256) fixup(const float* __restrict__ x,
                                             const float* __restrict__ c,
                                             const float* __restrict__ betas,
                                             float* __restrict__ out) {
    const int b = blockIdx.x;
    const float t = g_rx[b];
    if (t < g_glo || t > g_ghi) return;   // provably-zero row (NaN falls through)

    const int tid = threadIdx.x;
    __shared__ float xs[D_DIM];
    reinterpret_cast<float4*>(xs)[tid] =
        reinterpret_cast<const float4*>(x + (size_t)b * D_DIM)[tid];
    __syncthreads();
    const float sx = g_x2[b];
    float4* __restrict__ orow = reinterpret_cast<float4*>(out + (size_t)b * K_COLS);

    #pragma unroll
    for (int j = 0; j < 4; j++) {
        const int kq = tid + 256 * j;                       // float4 column group
        const float4 lo4 = reinterpret_cast<const float4*>(g_lo)[kq];
        const float4 hi4 = reinterpret_cast<const float4*>(g_hi)[kq];
        const float4 c24 = reinterpret_cast<const float4*>(g_c2)[kq];
        const float4 bt4 = reinterpret_cast<const float4*>(betas)[kq];
        const float lo_a[4] = {lo4.x, lo4.y, lo4.z, lo4.w};
        const float hi_a[4] = {hi4.x, hi4.y, hi4.z, hi4.w};
        const float c2_a[4] = {c24.x, c24.y, c24.z, c24.w};
        const float bt_a[4] = {bt4.x, bt4.y, bt4.z, bt4.w};
        float o[4];
        #pragma unroll
        for (int q = 0; q < 4; q++) {
            if (t < lo_a[q] || t > hi_a[q]) {
                o[q] = 0.0f;                                // provably underflows
            } else {
                const float* __restrict__ cr = c + (size_t)(kq * 4 + q) * D_DIM;
                float dot = 0.f;
                #pragma unroll 8
                for (int i = 0; i < D_DIM; i++) dot = fmaf(xs[i], cr[i], dot);
                const float d2 = fmaxf(sx + c2_a[q] - 2.0f * dot, 0.0f);
                o[q] = expf(-bt_a[q] * d2);
            }
        }
        orow[kq] = make_float4(o[0], o[1], o[2], o[3]);
    }
}

// ---------------------------------------------------------------------------
extern "C" void kernel_launch(void* const* d_in, const int* in_sizes, int n_in,
                              void* d_out, int out_size) {
    const float* x     = (const float*)d_in[0];
    const float* cent  = (const float*)d_in[1];
    const float* betas = (const float*)d_in[2];
    float* out = (float*)d_out;

    dim3 zgrid(K_COLS / 1024, B_ROWS);                 // 4 x 16384 CTAs
    zfill<<<zgrid, 256>>>(reinterpret_cast<float4*>(out));
    norms_kernel<<<K_COLS + B_ROWS, 256>>>(x, cent, betas);
    glob_kernel<<<1, 256>>>();
    fixup<<<B_ROWS, 256>>>(x, cent, betas, out);
}